// round 5
// baseline (speedup 1.0000x reference)
#include <cuda_runtime.h>

// Quanvolution via closed-form expectation values (Heisenberg picture):
//   a0 = x0 + w0, a1 = x1 + w1
//   <Z0> = cos(w2)*cos(a0); <Z1> = cos(a1); <Z2> = cos(a0)*cos(x2)
//   <Z3> = cos(w3)*cos(a0)*cos(x2)*cos(x3)
//
// Input  x: [32,1,512,512] fp32 -> Output [32,4,256,256] fp32
//
// Each thread: 4 adjacent patches. Four INDEPENDENT float4 loads issued
// up front (256B in flight per warp -> high L2 MLP), one float4 store per
// output plane. NO streaming cache hints: the 67MB working set stays
// L2-resident across graph replays.

#define HP      256
#define WP      256
#define PLANE   (HP * WP)                         // 65536
#define NTHREADS_TOTAL (32 * HP * (WP / 4))       // 524,288

__global__ __launch_bounds__(256, 8)
void quanv_kernel(const float* __restrict__ x,
                  const float* __restrict__ w,
                  float* __restrict__ out) {
    int idx = blockIdx.x * blockDim.x + threadIdx.x;   // [0, 524288)
    int kk = idx & 63;             // group of 4 patches (8 input columns)
    int j  = (idx >> 6) & 255;     // patch row
    int b  = idx >> 14;            // batch

    // input rows 2j, 2j+1; columns [8*kk, 8*kk+8)
    const float4* row0 = reinterpret_cast<const float4*>(
        x + ((size_t)b * 512 + 2 * (size_t)j) * 512) + 2 * kk;
    const float4* row1 = row0 + 128;   // +512 floats = next row

    // issue all four independent loads before anything depends on them
    float4 r0a = __ldg(row0);
    float4 r0b = __ldg(row0 + 1);
    float4 r1a = __ldg(row1);
    float4 r1b = __ldg(row1 + 1);

    const float w0  = __ldg(w + 0);
    const float w1  = __ldg(w + 1);
    const float cw2 = __cosf(__ldg(w + 2));
    const float cw3 = __cosf(__ldg(w + 3));

    // patch 0: (r0a.x, r0a.y, r1a.x, r1a.y)
    // patch 1: (r0a.z, r0a.w, r1a.z, r1a.w)
    // patch 2: (r0b.x, r0b.y, r1b.x, r1b.y)
    // patch 3: (r0b.z, r0b.w, r1b.z, r1b.w)
    float c0_0 = __cosf(r0a.x + w0);
    float c0_1 = __cosf(r0a.z + w0);
    float c0_2 = __cosf(r0b.x + w0);
    float c0_3 = __cosf(r0b.z + w0);

    float c1_0 = __cosf(r0a.y + w1);
    float c1_1 = __cosf(r0a.w + w1);
    float c1_2 = __cosf(r0b.y + w1);
    float c1_3 = __cosf(r0b.w + w1);

    float x2_0 = __cosf(r1a.x);
    float x2_1 = __cosf(r1a.z);
    float x2_2 = __cosf(r1b.x);
    float x2_3 = __cosf(r1b.z);

    float x3_0 = __cosf(r1a.y);
    float x3_1 = __cosf(r1a.w);
    float x3_2 = __cosf(r1b.y);
    float x3_3 = __cosf(r1b.w);

    float e2_0 = c0_0 * x2_0;
    float e2_1 = c0_1 * x2_1;
    float e2_2 = c0_2 * x2_2;
    float e2_3 = c0_3 * x2_3;

    float* o = out + (((size_t)b * 4) * HP + j) * WP + 4 * (size_t)kk;

    *reinterpret_cast<float4*>(o) =
        make_float4(cw2 * c0_0, cw2 * c0_1, cw2 * c0_2, cw2 * c0_3);
    *reinterpret_cast<float4*>(o + PLANE) =
        make_float4(c1_0, c1_1, c1_2, c1_3);
    *reinterpret_cast<float4*>(o + 2 * PLANE) =
        make_float4(e2_0, e2_1, e2_2, e2_3);
    *reinterpret_cast<float4*>(o + 3 * PLANE) =
        make_float4(cw3 * e2_0 * x3_0, cw3 * e2_1 * x3_1,
                    cw3 * e2_2 * x3_2, cw3 * e2_3 * x3_3);
}

extern "C" void kernel_launch(void* const* d_in, const int* in_sizes, int n_in,
                              void* d_out, int out_size) {
    const float* x = (const float*)d_in[0];
    const float* w = (const float*)d_in[1];
    float* out = (float*)d_out;

    dim3 block(256);
    dim3 grid(NTHREADS_TOTAL / 256);   // 2048 blocks
    quanv_kernel<<<grid, block>>>(x, w, out);
}

// round 6
// speedup vs baseline: 1.0328x; 1.0328x over previous
#include <cuda_runtime.h>
#include <cstdint>

// Quanvolution via closed-form expectation values:
//   a0 = x0 + w0, a1 = x1 + w1
//   <Z0> = cos(w2)*cos(a0); <Z1> = cos(a1); <Z2> = cos(a0)*cos(x2)
//   <Z3> = cos(w3)*cos(a0)*cos(x2)*cos(x3)
//
// Input  x: [32,1,512,512] fp32 -> Output [32,4,256,256] fp32
//
// Key layout fact: the patch row-pair (rows 2j,2j+1) of batch b is a
// CONTIGUOUS 4KB block at byte offset 4096*p, p = b*256+j, p in [0,8192).
// We stream these blocks with cp.async.bulk (TMA-class bulk engine) into a
// depth-4 smem pipeline behind mbarriers — the bulk engine keeps far more
// bytes in flight than per-thread LDG can, breaking the ~3TB/s latency bind.
// 1024 CTAs x 8 row-pairs each; all CTAs resident in one wave.

#define PLANE       65536
#define STAGES      4
#define STAGE_BYTES 4096
#define ITERS       8
#define NCTA        1024

__device__ __forceinline__ uint32_t smem_u32(const void* p) {
    uint32_t a;
    asm("{ .reg .u64 t; cvta.to.shared.u64 t, %1; cvt.u32.u64 %0, t; }"
        : "=r"(a) : "l"(p));
    return a;
}

__global__ __launch_bounds__(256, 8)
void quanv_kernel(const float* __restrict__ x,
                  const float* __restrict__ w,
                  float* __restrict__ out) {
    __shared__ alignas(8) unsigned long long mbar[STAGES];
    __shared__ alignas(128) float stage[STAGES][STAGE_BYTES / 4];

    const int tid = threadIdx.x;
    const int p0  = blockIdx.x * ITERS;   // first row-pair of this CTA

    if (tid == 0) {
        #pragma unroll
        for (int s = 0; s < STAGES; s++) {
            uint32_t mb = smem_u32(&mbar[s]);
            asm volatile("mbarrier.init.shared.b64 [%0], %1;"
                         :: "r"(mb), "r"(1) : "memory");
        }
    }
    __syncthreads();

    // prologue: fill all 4 stages
    if (tid == 0) {
        #pragma unroll
        for (int s = 0; s < STAGES; s++) {
            uint32_t mb = smem_u32(&mbar[s]);
            uint32_t dst = smem_u32(&stage[s][0]);
            const float* src = x + (size_t)(p0 + s) * 1024;
            asm volatile("mbarrier.arrive.expect_tx.shared.b64 _, [%0], %1;"
                         :: "r"(mb), "r"(STAGE_BYTES) : "memory");
            asm volatile(
                "cp.async.bulk.shared::cta.global.mbarrier::complete_tx::bytes "
                "[%0], [%1], %2, [%3];"
                :: "r"(dst), "l"(src), "r"(STAGE_BYTES), "r"(mb) : "memory");
        }
    }

    const float w0  = __ldg(w + 0);
    const float w1  = __ldg(w + 1);
    const float cw2 = __cosf(__ldg(w + 2));
    const float cw3 = __cosf(__ldg(w + 3));

    #pragma unroll
    for (int it = 0; it < ITERS; it++) {
        const int s  = it & (STAGES - 1);
        const int ph = (it >> 2) & 1;
        uint32_t mb = smem_u32(&mbar[s]);

        // wait for stage s to be full (phase parity ph)
        {
            uint32_t done;
            asm volatile(
                "{\n\t.reg .pred p;\n\t"
                "mbarrier.try_wait.parity.acquire.cta.shared::cta.b64 p, [%1], %2;\n\t"
                "selp.b32 %0, 1, 0, p;\n\t}"
                : "=r"(done) : "r"(mb), "r"(ph) : "memory");
            if (!done) {
                asm volatile(
                    "{\n\t.reg .pred P1;\n\t"
                    "W_%=:\n\t"
                    "mbarrier.try_wait.parity.acquire.cta.shared::cta.b64 P1, [%0], %1;\n\t"
                    "@P1 bra.uni D_%=;\n\t"
                    "bra.uni W_%=;\n\t"
                    "D_%=:\n\t}"
                    :: "r"(mb), "r"(ph) : "memory");
            }
        }

        // compute: thread tid handles patch tid of row-pair p0+it
        const int p = p0 + it;
        const int b = p >> 8;
        const int j = p & 255;

        float2 top = *reinterpret_cast<const float2*>(&stage[s][2 * tid]);
        float2 bot = *reinterpret_cast<const float2*>(&stage[s][512 + 2 * tid]);

        float c0 = __cosf(top.x + w0);
        float c1 = __cosf(top.y + w1);
        float c2 = __cosf(bot.x);
        float c3 = __cosf(bot.y);
        float e2 = c0 * c2;

        float* o = out + ((size_t)b * 4) * PLANE + (size_t)j * 256 + tid;
        o[0]         = cw2 * c0;
        o[PLANE]     = c1;
        o[2 * PLANE] = e2;
        o[3 * PLANE] = cw3 * e2 * c3;

        __syncthreads();   // everyone done reading stage s

        // refill stage s for iteration it+4
        if (tid == 0 && it < ITERS - STAGES) {
            uint32_t dst = smem_u32(&stage[s][0]);
            const float* src = x + (size_t)(p0 + it + STAGES) * 1024;
            asm volatile("mbarrier.arrive.expect_tx.shared.b64 _, [%0], %1;"
                         :: "r"(mb), "r"(STAGE_BYTES) : "memory");
            asm volatile(
                "cp.async.bulk.shared::cta.global.mbarrier::complete_tx::bytes "
                "[%0], [%1], %2, [%3];"
                :: "r"(dst), "l"(src), "r"(STAGE_BYTES), "r"(mb) : "memory");
        }
    }
}

extern "C" void kernel_launch(void* const* d_in, const int* in_sizes, int n_in,
                              void* d_out, int out_size) {
    const float* x = (const float*)d_in[0];
    const float* w = (const float*)d_in[1];
    float* out = (float*)d_out;

    quanv_kernel<<<NCTA, 256>>>(x, w, out);
}